// round 7
// baseline (speedup 1.0000x reference)
#include <cuda_runtime.h>
#include <cuda_fp16.h>
#include <mma.h>
#include <cstdint>

using namespace nvcuda;

// Problem constants (fixed by dataset)
#define Nn 50000
#define Dd 128
#define Rr 3
#define Ee 800000
#define OUTD 64
#define ALPHAc 0.5f
#define BETA1c 0.6931471805599453f   // ln 2
#define BETA2c 0.4054651081081644f   // ln 1.5
#define SLOPEc 0.01f

// ---------------- scratch (device globals; no allocations allowed) ----------
__device__ __align__(256) __half g_xs  [(size_t)Rr * Nn * Dd];        // prescaled x (dinv_out)
__device__ __align__(256) __half g_h1s [(size_t)Rr * Nn * Dd];        // prescaled h1 (dinv_out)
__device__ __align__(256) __half g_aggh[((size_t)Rr * Nn + 64) * Dd]; // layer operand (complete), padded
__device__ __align__(256) __half g_xh  [((size_t)Nn + 64) * Dd];      // plain fp16 x, padded
__device__ __align__(256) __half g_W1h [Rr * Dd * Dd];                // b1*W1 + (1-b1)*I
__device__ __align__(256) __half g_Gh  [Rr * Dd * OUTD];
__device__ __align__(256) __half g_Gxh [Dd * OUTD];
__device__ int   g_deg_out[Rr * Nn];
__device__ int   g_deg_in[Rr * Nn];
__device__ float g_dinv_out[Rr * Nn];
__device__ float g_dinv_in[Rr * Nn];
__device__ int   g_rowstart[Rr * Nn];
__device__ int   g_fillcur[Rr * Nn];
__device__ int   g_col[(size_t)Rr * Ee];
__device__ int   g_cursor[Rr];
__device__ float g_G[Rr * Dd * OUTD];
__device__ float g_c[OUTD];

// ---------------- init small state -------------------------------------------
__global__ void k_init() {
    int i = blockIdx.x * blockDim.x + threadIdx.x;
    if (i < Rr * Nn) { g_deg_out[i] = 0; g_deg_in[i] = 0; }
    if (i < Rr) g_cursor[i] = 0;
}

// ---------------- degree histogram: 4 edges per thread ------------------------
__global__ void k_degree(const int* __restrict__ src, const int* __restrict__ dst) {
    int i4 = blockIdx.x * blockDim.x + threadIdx.x;
    if (i4 >= Rr * Ee / 4) return;
    int r = (i4 * 4) / Ee;                 // Ee % 4 == 0: group stays in one relation
    int4 s = __ldg(reinterpret_cast<const int4*>(src) + i4);
    int4 d = __ldg(reinterpret_cast<const int4*>(dst) + i4);
    int* po = g_deg_out + r * Nn;
    int* pi = g_deg_in + r * Nn;
    atomicAdd(po + s.x, 1); atomicAdd(po + s.y, 1);
    atomicAdd(po + s.z, 1); atomicAdd(po + s.w, 1);
    atomicAdd(pi + d.x, 1); atomicAdd(pi + d.y, 1);
    atomicAdd(pi + d.z, 1); atomicAdd(pi + d.w, 1);
}

// ---------------- row starts via warp-aggregated scan + dinv ------------------
__global__ void k_rowstart() {
    int r = blockIdx.y;
    int n = blockIdx.x * blockDim.x + threadIdx.x;
    int lane = threadIdx.x & 31;
    int d = (n < Nn) ? g_deg_in[r * Nn + n] : 0;
    int incl = d;
#pragma unroll
    for (int o = 1; o < 32; o <<= 1) {
        int v = __shfl_up_sync(0xffffffffu, incl, o);
        if (lane >= o) incl += v;
    }
    int total = __shfl_sync(0xffffffffu, incl, 31);
    int base = 0;
    if (lane == 31) base = atomicAdd(&g_cursor[r], total);
    base = __shfl_sync(0xffffffffu, base, 31);
    if (n < Nn) {
        int start = r * Ee + base + incl - d;
        g_rowstart[r * Nn + n] = start;
        g_fillcur [r * Nn + n] = start;
        int di = d < 1 ? 1 : d;
        g_dinv_in[r * Nn + n] = rsqrtf((float)di);
        int doo = g_deg_out[r * Nn + n]; if (doo < 1) doo = 1;
        g_dinv_out[r * Nn + n] = rsqrtf((float)doo);
    }
}

// ---------------- CSR fill: 4 edges per thread ---------------------------------
__global__ void k_csrfill(const int* __restrict__ src, const int* __restrict__ dst) {
    int i4 = blockIdx.x * blockDim.x + threadIdx.x;
    if (i4 >= Rr * Ee / 4) return;
    int r = (i4 * 4) / Ee;
    int4 s = __ldg(reinterpret_cast<const int4*>(src) + i4);
    int4 d = __ldg(reinterpret_cast<const int4*>(dst) + i4);
    int* fc = g_fillcur + r * Nn;
    int p0 = atomicAdd(fc + d.x, 1);
    int p1 = atomicAdd(fc + d.y, 1);
    int p2 = atomicAdd(fc + d.z, 1);
    int p3 = atomicAdd(fc + d.w, 1);
    g_col[p0] = s.x; g_col[p1] = s.y; g_col[p2] = s.z; g_col[p3] = s.w;
}

// ---------------- prescale: read x once, write xh + 3 prescaled copies --------
__global__ void k_prescale(const float* __restrict__ x) {
    int i = blockIdx.x * blockDim.x + threadIdx.x;      // one per 4 elems of one node
    if (i >= Nn * (Dd / 4)) return;
    int c4 = i & 31;
    int n = i >> 5;
    float4 v = __ldg(reinterpret_cast<const float4*>(x + (size_t)n * Dd) + c4);
    __half2 q0 = __floats2half2_rn(v.x, v.y);
    __half2 q1 = __floats2half2_rn(v.z, v.w);
    uint2 w;
    w.x = *reinterpret_cast<unsigned*>(&q0);
    w.y = *reinterpret_cast<unsigned*>(&q1);
    *reinterpret_cast<uint2*>(g_xh + (size_t)n * Dd + c4 * 4) = w;
#pragma unroll
    for (int r = 0; r < Rr; ++r) {
        float s = __ldg(g_dinv_out + r * Nn + n);
        __half2 p0 = __floats2half2_rn(v.x * s, v.y * s);
        __half2 p1 = __floats2half2_rn(v.z * s, v.w * s);
        uint2 u;
        u.x = *reinterpret_cast<unsigned*>(&p0);
        u.y = *reinterpret_cast<unsigned*>(&p1);
        *reinterpret_cast<uint2*>(g_xs + ((size_t)r * Nn + n) * Dd + c4 * 4) = u;
    }
}

// ---------------- precompute folded layer-2 matrices --------------------------
__global__ void k_prep1(const float* __restrict__ W2, const float* __restrict__ Wlin) {
    int r = blockIdx.x >> 7;
    int i = blockIdx.x & 127;
    int j = threadIdx.x;              // 0..63
    const float* wrow = W2 + ((size_t)r * Dd + i) * Dd;
    float s = 0.f;
#pragma unroll 8
    for (int k = 0; k < Dd; ++k) s += wrow[k] * Wlin[k * OUTD + j];
    g_G[((size_t)r * Dd + i) * OUTD + j] = BETA2c * s + (1.f - BETA2c) * Wlin[i * OUTD + j];
}

// scale + convert to fp16 in one pass; also compute c
__global__ void k_prep2(const float* __restrict__ b2, const float* __restrict__ Wlin,
                        const float* __restrict__ blin) {
    int idx = blockIdx.x * blockDim.x + threadIdx.x;
    if (idx < Dd * OUTD) {
        float v0 = g_G[idx], v1 = g_G[Dd * OUTD + idx], v2 = g_G[2 * Dd * OUTD + idx];
        g_Gxh[idx] = __float2half((ALPHAc / 3.f) * (v0 + v1 + v2));
        const float sc = (1.f - ALPHAc) / 3.f;
        g_Gh[idx]                = __float2half(v0 * sc);
        g_Gh[Dd * OUTD + idx]    = __float2half(v1 * sc);
        g_Gh[2 * Dd * OUTD + idx] = __float2half(v2 * sc);
    }
    if (idx < OUTD) {
        float cc = blin[idx];
        for (int k = 0; k < Dd; ++k)
            cc += (b2[k] + b2[Dd + k] + b2[2 * Dd + k]) * (1.f / 3.f) * Wlin[k * OUTD + idx];
        g_c[idx] = cc;
    }
}

// W1' = b1*W1 + (1-b1)*I, fp16
__global__ void k_prepw1(const float* __restrict__ W1) {
    int idx = blockIdx.x * blockDim.x + threadIdx.x;
    if (idx >= Rr * Dd * Dd) return;
    int ij = idx % (Dd * Dd);
    int i = ij >> 7, j = ij & 127;
    float v = BETA1c * W1[idx] + ((i == j) ? (1.f - BETA1c) : 0.f);
    g_W1h[idx] = __float2half(v);
}

// ---------------- fp16 gather helpers ------------------------------------------
__device__ __forceinline__ void acc_h4(float4& acc, uint2 u) {
    __half2 a = *reinterpret_cast<__half2*>(&u.x);
    __half2 b = *reinterpret_cast<__half2*>(&u.y);
    float2 fa = __half22float2(a), fb = __half22float2(b);
    acc.x += fa.x; acc.y += fa.y; acc.z += fb.x; acc.w += fb.y;
}

// ---------------- gather: one warp per (r,n); produces COMPLETE layer operand --
// which=0: aggh = (1-a)*dinv_in*sum + a*x   (layer-1 rst, fp16)
// which=1: aggh = dinv_in*sum               (layer-2 A operand)
__launch_bounds__(256)
__global__ void k_gather(int which) {
    int gw = (blockIdx.x * blockDim.x + threadIdx.x) >> 5;   // (r,n) index
    if (gw >= Rr * Nn) return;
    int lane = threadIdx.x & 31;
    int n = gw % Nn;
    const __half* base = (which ? g_h1s : g_xs) + (size_t)(gw / Nn) * Nn * Dd;

    int beg = __ldg(g_rowstart + gw);
    int end = beg + __ldg(g_deg_in + gw);
    float4 acc = make_float4(0.f, 0.f, 0.f, 0.f);
    int e = beg;
#pragma unroll 1
    for (; e + 4 <= end; e += 4) {
        int s0 = __ldg(g_col + e);
        int s1 = __ldg(g_col + e + 1);
        int s2 = __ldg(g_col + e + 2);
        int s3 = __ldg(g_col + e + 3);
        uint2 u0 = __ldg(reinterpret_cast<const uint2*>(base + (size_t)s0 * Dd) + lane);
        uint2 u1 = __ldg(reinterpret_cast<const uint2*>(base + (size_t)s1 * Dd) + lane);
        uint2 u2 = __ldg(reinterpret_cast<const uint2*>(base + (size_t)s2 * Dd) + lane);
        uint2 u3 = __ldg(reinterpret_cast<const uint2*>(base + (size_t)s3 * Dd) + lane);
        acc_h4(acc, u0); acc_h4(acc, u1); acc_h4(acc, u2); acc_h4(acc, u3);
    }
#pragma unroll 1
    for (; e < end; ++e) {
        int s0 = __ldg(g_col + e);
        uint2 u0 = __ldg(reinterpret_cast<const uint2*>(base + (size_t)s0 * Dd) + lane);
        acc_h4(acc, u0);
    }
    float sc = __ldg(g_dinv_in + gw) * (which ? 1.f : (1.f - ALPHAc));
    float4 o;
    if (which) {
        o.x = acc.x * sc; o.y = acc.y * sc; o.z = acc.z * sc; o.w = acc.w * sc;
    } else {
        uint2 xv = __ldg(reinterpret_cast<const uint2*>(g_xh + (size_t)n * Dd) + lane);
        float4 xf = make_float4(0.f, 0.f, 0.f, 0.f);
        acc_h4(xf, xv);
        o.x = acc.x * sc + ALPHAc * xf.x;
        o.y = acc.y * sc + ALPHAc * xf.y;
        o.z = acc.z * sc + ALPHAc * xf.z;
        o.w = acc.w * sc + ALPHAc * xf.w;
    }
    __half2 p0 = __floats2half2_rn(o.x, o.y);
    __half2 p1 = __floats2half2_rn(o.z, o.w);
    uint2 u;
    u.x = *reinterpret_cast<unsigned*>(&p0);
    u.y = *reinterpret_cast<unsigned*>(&p1);
    *reinterpret_cast<uint2*>(g_aggh + (size_t)gw * Dd + lane * 4) = u;
}

// pack 8 scaled floats -> 8 halfs (16B)
__device__ __forceinline__ uint4 pack_half8(const float* v, float s) {
    __half2 p0 = __floats2half2_rn(v[0] * s, v[1] * s);
    __half2 p1 = __floats2half2_rn(v[2] * s, v[3] * s);
    __half2 p2 = __floats2half2_rn(v[4] * s, v[5] * s);
    __half2 p3 = __floats2half2_rn(v[6] * s, v[7] * s);
    uint4 u;
    u.x = *reinterpret_cast<unsigned*>(&p0);
    u.y = *reinterpret_cast<unsigned*>(&p1);
    u.z = *reinterpret_cast<unsigned*>(&p2);
    u.w = *reinterpret_cast<unsigned*>(&p3);
    return u;
}

// ---------------- layer-1 GEMM: A direct from global, tensor cores ------------
// C = aggh_r @ W1'_r ; epi: +bias, leaky, 1/3 mean; writes prescaled h1s
__launch_bounds__(256)
__global__ void k_gemm1(const float* __restrict__ b1) {
    __shared__ __align__(16) float Cs[64 * 132];   // 33792 B
    int tid = threadIdx.x;
    int warp = tid >> 5;
    int ty = tid >> 4, tx = tid & 15;
    int wr = warp >> 1, wc = warp & 1;
    int n0 = blockIdx.x << 6;

    float hacc[4][8];
#pragma unroll
    for (int i = 0; i < 4; ++i)
#pragma unroll
        for (int j = 0; j < 8; ++j) hacc[i][j] = 0.f;

    for (int r = 0; r < Rr; ++r) {
        wmma::fragment<wmma::accumulator, 16, 16, 16, float> acc[4];
#pragma unroll
        for (int f = 0; f < 4; ++f) wmma::fill_fragment(acc[f], 0.f);
        const __half* Ab = g_aggh + ((size_t)r * Nn + n0) * Dd;
        const __half* Bg = g_W1h + (size_t)r * Dd * Dd;
#pragma unroll
        for (int k = 0; k < 8; ++k) {
            wmma::fragment<wmma::matrix_a, 16, 16, 16, __half, wmma::row_major> af;
            wmma::load_matrix_sync(af, Ab + (size_t)(wr * 16) * Dd + k * 16, Dd);
#pragma unroll
            for (int f = 0; f < 4; ++f) {
                wmma::fragment<wmma::matrix_b, 16, 16, 16, __half, wmma::row_major> bf;
                wmma::load_matrix_sync(bf, Bg + (k * 16) * Dd + wc * 64 + f * 16, Dd);
                wmma::mma_sync(acc[f], af, bf, acc[f]);
            }
        }
        if (r > 0) __syncthreads();   // previous epilogue reads done before overwrite
#pragma unroll
        for (int f = 0; f < 4; ++f)
            wmma::store_matrix_sync(Cs + (wr * 16) * 132 + wc * 64 + f * 16, acc[f], 132,
                                    wmma::mem_row_major);
        __syncthreads();

        // epilogue: +bias, leaky, 1/3 mean
#pragma unroll
        for (int i = 0; i < 4; ++i) {
            int row = ty * 4 + i;
#pragma unroll
            for (int j = 0; j < 8; ++j) {
                int col = tx * 8 + j;
                float v = Cs[row * 132 + col] + b1[r * Dd + col];
                v = v >= 0.f ? v : SLOPEc * v;
                hacc[i][j] += v * (1.f / 3.f);
            }
        }
    }

    // write prescaled fp16 h1s for each relation
#pragma unroll
    for (int i = 0; i < 4; ++i) {
        int n = n0 + ty * 4 + i;
        if (n < Nn) {
#pragma unroll
            for (int r = 0; r < Rr; ++r) {
                float s = g_dinv_out[r * Nn + n];
                uint4 u = pack_half8(hacc[i], s);
                *reinterpret_cast<uint4*>(g_h1s + ((size_t)r * Nn + n) * Dd + tx * 8) = u;
            }
        }
    }
}

// ---------------- layer-2 GEMM + output projection: tensor cores ----------------
__launch_bounds__(256)
__global__ void k_gemm2(float* __restrict__ out) {
    __shared__ __align__(16) float Cs[64 * 68];
    int tid = threadIdx.x;
    int warp = tid >> 5;
    int ty = tid >> 4, tx = tid & 15;
    int wr = warp >> 1, wc = warp & 1;
    int n0 = blockIdx.x << 6;

    wmma::fragment<wmma::accumulator, 16, 16, 16, float> acc[2];
#pragma unroll
    for (int f = 0; f < 2; ++f) wmma::fill_fragment(acc[f], 0.f);

#pragma unroll 1
    for (int seg = 0; seg < 4; ++seg) {
        const __half* Ab = (seg < 3) ? (g_aggh + ((size_t)seg * Nn + n0) * Dd)
                                     : (g_xh + (size_t)n0 * Dd);
        const __half* Bb = (seg < 3) ? (g_Gh + (size_t)seg * Dd * OUTD) : g_Gxh;
#pragma unroll
        for (int k = 0; k < 8; ++k) {
            wmma::fragment<wmma::matrix_a, 16, 16, 16, __half, wmma::row_major> af;
            wmma::load_matrix_sync(af, Ab + (size_t)(wr * 16) * Dd + k * 16, Dd);
#pragma unroll
            for (int f = 0; f < 2; ++f) {
                wmma::fragment<wmma::matrix_b, 16, 16, 16, __half, wmma::row_major> bf;
                wmma::load_matrix_sync(bf, Bb + (k * 16) * OUTD + wc * 32 + f * 16, OUTD);
                wmma::mma_sync(acc[f], af, bf, acc[f]);
            }
        }
    }
#pragma unroll
    for (int f = 0; f < 2; ++f)
        wmma::store_matrix_sync(Cs + (wr * 16) * 68 + wc * 32 + f * 16, acc[f], 68,
                                wmma::mem_row_major);
    __syncthreads();

#pragma unroll
    for (int i = 0; i < 4; ++i) {
        int n = n0 + ty * 4 + i;
        if (n < Nn) {
            int row = ty * 4 + i;
            float4 o;
            o.x = Cs[row * 68 + tx * 4 + 0] + g_c[tx * 4 + 0];
            o.y = Cs[row * 68 + tx * 4 + 1] + g_c[tx * 4 + 1];
            o.z = Cs[row * 68 + tx * 4 + 2] + g_c[tx * 4 + 2];
            o.w = Cs[row * 68 + tx * 4 + 3] + g_c[tx * 4 + 3];
            *reinterpret_cast<float4*>(out + (size_t)n * OUTD + tx * 4) = o;
        }
    }
}

// ---------------- launch ------------------------------------------------------
extern "C" void kernel_launch(void* const* d_in, const int* in_sizes, int n_in,
                              void* d_out, int out_size) {
    const float* x    = (const float*)d_in[0];
    const int*   src  = (const int*)  d_in[1];
    const int*   dst  = (const int*)  d_in[2];
    const float* W1   = (const float*)d_in[3];
    const float* b1   = (const float*)d_in[4];
    const float* W2   = (const float*)d_in[5];
    const float* b2   = (const float*)d_in[6];
    const float* Wlin = (const float*)d_in[7];
    const float* blin = (const float*)d_in[8];
    float* out = (float*)d_out;

    k_init<<<(Rr * Nn + 255) / 256, 256>>>();
    k_degree<<<(Rr * Ee / 4 + 255) / 256, 256>>>(src, dst);
    dim3 rsgrid((Nn + 255) / 256, Rr);
    k_rowstart<<<rsgrid, 256>>>();
    k_csrfill<<<(Rr * Ee / 4 + 255) / 256, 256>>>(src, dst);
    k_prescale<<<(Nn * (Dd / 4) + 255) / 256, 256>>>(x);
    k_prep1<<<Rr * Dd, OUTD>>>(W2, Wlin);
    k_prep2<<<32, 256>>>(b2, Wlin, blin);
    k_prepw1<<<(Rr * Dd * Dd + 255) / 256, 256>>>(W1);

    const int gather_blocks = (Rr * Nn * 32 + 255) / 256;   // one warp per (r,n)
    // layer 1
    k_gather<<<gather_blocks, 256>>>(0);
    k_gemm1<<<(Nn + 63) / 64, 256>>>(b1);
    // layer 2
    k_gather<<<gather_blocks, 256>>>(1);
    k_gemm2<<<(Nn + 63) / 64, 256>>>(out);
}

// round 8
// speedup vs baseline: 1.1059x; 1.1059x over previous
#include <cuda_runtime.h>
#include <cuda_fp16.h>
#include <mma.h>
#include <cstdint>

using namespace nvcuda;

// Problem constants (fixed by dataset)
#define Nn 50000
#define Dd 128
#define Rr 3
#define Ee 800000
#define OUTD 64
#define ALPHAc 0.5f
#define BETA1c 0.6931471805599453f   // ln 2
#define BETA2c 0.4054651081081644f   // ln 1.5
#define SLOPEc 0.01f

// ---------------- scratch (device globals; no allocations allowed) ----------
__device__ __align__(256) __half g_xs  [(size_t)Rr * Nn * Dd];        // prescaled x (dinv_out)
__device__ __align__(256) __half g_h1s [(size_t)Rr * Nn * Dd];        // prescaled h1 (dinv_out)
__device__ __align__(256) __half g_aggh[((size_t)Rr * Nn + 64) * Dd]; // complete layer operand, padded
__device__ __align__(256) __half g_xh  [((size_t)Nn + 64) * Dd];      // plain fp16 x, padded
__device__ __align__(256) __half g_W1h [Rr * Dd * Dd];                // b1*W1 + (1-b1)*I
__device__ __align__(256) __half g_Gh  [Rr * Dd * OUTD];
__device__ __align__(256) __half g_Gxh [Dd * OUTD];
__device__ int   g_deg_out[Rr * Nn];
__device__ int   g_deg_in[Rr * Nn];
__device__ float g_dinv_out[Rr * Nn];
__device__ float g_dinv_in[Rr * Nn];
__device__ int   g_rowstart[Rr * Nn];
__device__ int   g_fillcur[Rr * Nn];
__device__ int   g_col[(size_t)Rr * Ee];
__device__ int   g_cursor[Rr];
__device__ float g_G[Rr * Dd * OUTD];
__device__ float g_c[OUTD];

// ---------------- init small state -------------------------------------------
__global__ void k_init() {
    int i = blockIdx.x * blockDim.x + threadIdx.x;
    if (i < Rr * Nn) { g_deg_out[i] = 0; g_deg_in[i] = 0; }
    if (i < Rr) g_cursor[i] = 0;
}

// ---------------- degree histogram ---------------------------------------------
__global__ void k_degree(const int* __restrict__ src, const int* __restrict__ dst) {
    int i = blockIdx.x * blockDim.x + threadIdx.x;
    if (i >= Rr * Ee) return;
    int r = i / Ee;
    atomicAdd(&g_deg_out[r * Nn + src[i]], 1);
    atomicAdd(&g_deg_in [r * Nn + dst[i]], 1);
}

// ---------------- row starts via warp-aggregated scan + dinv ------------------
__global__ void k_rowstart() {
    int r = blockIdx.y;
    int n = blockIdx.x * blockDim.x + threadIdx.x;
    int lane = threadIdx.x & 31;
    int d = (n < Nn) ? g_deg_in[r * Nn + n] : 0;
    int incl = d;
#pragma unroll
    for (int o = 1; o < 32; o <<= 1) {
        int v = __shfl_up_sync(0xffffffffu, incl, o);
        if (lane >= o) incl += v;
    }
    int total = __shfl_sync(0xffffffffu, incl, 31);
    int base = 0;
    if (lane == 31) base = atomicAdd(&g_cursor[r], total);
    base = __shfl_sync(0xffffffffu, base, 31);
    if (n < Nn) {
        int start = r * Ee + base + incl - d;
        g_rowstart[r * Nn + n] = start;
        g_fillcur [r * Nn + n] = start;
        int di = d < 1 ? 1 : d;
        g_dinv_in[r * Nn + n] = rsqrtf((float)di);
        int doo = g_deg_out[r * Nn + n]; if (doo < 1) doo = 1;
        g_dinv_out[r * Nn + n] = rsqrtf((float)doo);
    }
}

// ---------------- CSR fill -----------------------------------------------------
__global__ void k_csrfill(const int* __restrict__ src, const int* __restrict__ dst) {
    int i = blockIdx.x * blockDim.x + threadIdx.x;
    if (i >= Rr * Ee) return;
    int r = i / Ee;
    int pos = atomicAdd(&g_fillcur[r * Nn + dst[i]], 1);
    g_col[pos] = src[i];
}

// ---------------- prescale: read x once, write xh + 3 prescaled copies --------
__global__ void k_prescale(const float* __restrict__ x) {
    int i = blockIdx.x * blockDim.x + threadIdx.x;      // one per 4 elems of one node
    if (i >= Nn * (Dd / 4)) return;
    int c4 = i & 31;
    int n = i >> 5;
    float4 v = __ldg(reinterpret_cast<const float4*>(x + (size_t)n * Dd) + c4);
    __half2 q0 = __floats2half2_rn(v.x, v.y);
    __half2 q1 = __floats2half2_rn(v.z, v.w);
    uint2 w;
    w.x = *reinterpret_cast<unsigned*>(&q0);
    w.y = *reinterpret_cast<unsigned*>(&q1);
    *reinterpret_cast<uint2*>(g_xh + (size_t)n * Dd + c4 * 4) = w;
#pragma unroll
    for (int r = 0; r < Rr; ++r) {
        float s = __ldg(g_dinv_out + r * Nn + n);
        __half2 p0 = __floats2half2_rn(v.x * s, v.y * s);
        __half2 p1 = __floats2half2_rn(v.z * s, v.w * s);
        uint2 u;
        u.x = *reinterpret_cast<unsigned*>(&p0);
        u.y = *reinterpret_cast<unsigned*>(&p1);
        *reinterpret_cast<uint2*>(g_xs + ((size_t)r * Nn + n) * Dd + c4 * 4) = u;
    }
}

// ---------------- precompute folded layer-2 matrices --------------------------
__global__ void k_prep1(const float* __restrict__ W2, const float* __restrict__ Wlin) {
    int r = blockIdx.x >> 7;
    int i = blockIdx.x & 127;
    int j = threadIdx.x;              // 0..63
    const float* wrow = W2 + ((size_t)r * Dd + i) * Dd;
    float s = 0.f;
#pragma unroll 8
    for (int k = 0; k < Dd; ++k) s += wrow[k] * Wlin[k * OUTD + j];
    g_G[((size_t)r * Dd + i) * OUTD + j] = BETA2c * s + (1.f - BETA2c) * Wlin[i * OUTD + j];
}

// scale + convert to fp16 in one pass; also compute c
__global__ void k_prep2(const float* __restrict__ b2, const float* __restrict__ Wlin,
                        const float* __restrict__ blin) {
    int idx = blockIdx.x * blockDim.x + threadIdx.x;
    if (idx < Dd * OUTD) {
        float v0 = g_G[idx], v1 = g_G[Dd * OUTD + idx], v2 = g_G[2 * Dd * OUTD + idx];
        g_Gxh[idx] = __float2half((ALPHAc / 3.f) * (v0 + v1 + v2));
        const float sc = (1.f - ALPHAc) / 3.f;
        g_Gh[idx]                 = __float2half(v0 * sc);
        g_Gh[Dd * OUTD + idx]     = __float2half(v1 * sc);
        g_Gh[2 * Dd * OUTD + idx] = __float2half(v2 * sc);
    }
    if (idx < OUTD) {
        float cc = blin[idx];
        for (int k = 0; k < Dd; ++k)
            cc += (b2[k] + b2[Dd + k] + b2[2 * Dd + k]) * (1.f / 3.f) * Wlin[k * OUTD + idx];
        g_c[idx] = cc;
    }
}

// W1' = b1*W1 + (1-b1)*I, fp16
__global__ void k_prepw1(const float* __restrict__ W1) {
    int idx = blockIdx.x * blockDim.x + threadIdx.x;
    if (idx >= Rr * Dd * Dd) return;
    int ij = idx % (Dd * Dd);
    int i = ij >> 7, j = ij & 127;
    float v = BETA1c * W1[idx] + ((i == j) ? (1.f - BETA1c) : 0.f);
    g_W1h[idx] = __float2half(v);
}

// ---------------- fp16 gather helpers ------------------------------------------
__device__ __forceinline__ void acc_h4(float4& acc, uint2 u) {
    __half2 a = *reinterpret_cast<__half2*>(&u.x);
    __half2 b = *reinterpret_cast<__half2*>(&u.y);
    float2 fa = __half22float2(a), fb = __half22float2(b);
    acc.x += fa.x; acc.y += fa.y; acc.z += fb.x; acc.w += fb.y;
}

// ---------------- gather: one warp per (r,n); produces COMPLETE layer operand --
// which=0: aggh = (1-a)*dinv_in*sum + a*x   (layer-1 rst, fp16)
// which=1: aggh = dinv_in*sum               (layer-2 A operand)
__launch_bounds__(256)
__global__ void k_gather(int which) {
    int gw = (blockIdx.x * blockDim.x + threadIdx.x) >> 5;   // (r,n) index
    if (gw >= Rr * Nn) return;
    int lane = threadIdx.x & 31;
    int n = gw % Nn;
    const __half* base = (which ? g_h1s : g_xs) + (size_t)(gw / Nn) * Nn * Dd;

    int beg = __ldg(g_rowstart + gw);
    int end = beg + __ldg(g_deg_in + gw);
    float4 acc = make_float4(0.f, 0.f, 0.f, 0.f);
    int e = beg;
#pragma unroll 1
    for (; e + 4 <= end; e += 4) {
        int s0 = __ldg(g_col + e);
        int s1 = __ldg(g_col + e + 1);
        int s2 = __ldg(g_col + e + 2);
        int s3 = __ldg(g_col + e + 3);
        uint2 u0 = __ldg(reinterpret_cast<const uint2*>(base + (size_t)s0 * Dd) + lane);
        uint2 u1 = __ldg(reinterpret_cast<const uint2*>(base + (size_t)s1 * Dd) + lane);
        uint2 u2 = __ldg(reinterpret_cast<const uint2*>(base + (size_t)s2 * Dd) + lane);
        uint2 u3 = __ldg(reinterpret_cast<const uint2*>(base + (size_t)s3 * Dd) + lane);
        acc_h4(acc, u0); acc_h4(acc, u1); acc_h4(acc, u2); acc_h4(acc, u3);
    }
#pragma unroll 1
    for (; e < end; ++e) {
        int s0 = __ldg(g_col + e);
        uint2 u0 = __ldg(reinterpret_cast<const uint2*>(base + (size_t)s0 * Dd) + lane);
        acc_h4(acc, u0);
    }
    float sc = __ldg(g_dinv_in + gw) * (which ? 1.f : (1.f - ALPHAc));
    float4 o;
    if (which) {
        o.x = acc.x * sc; o.y = acc.y * sc; o.z = acc.z * sc; o.w = acc.w * sc;
    } else {
        uint2 xv = __ldg(reinterpret_cast<const uint2*>(g_xh + (size_t)n * Dd) + lane);
        float4 xf = make_float4(0.f, 0.f, 0.f, 0.f);
        acc_h4(xf, xv);
        o.x = acc.x * sc + ALPHAc * xf.x;
        o.y = acc.y * sc + ALPHAc * xf.y;
        o.z = acc.z * sc + ALPHAc * xf.z;
        o.w = acc.w * sc + ALPHAc * xf.w;
    }
    __half2 p0 = __floats2half2_rn(o.x, o.y);
    __half2 p1 = __floats2half2_rn(o.z, o.w);
    uint2 u;
    u.x = *reinterpret_cast<unsigned*>(&p0);
    u.y = *reinterpret_cast<unsigned*>(&p1);
    *reinterpret_cast<uint2*>(g_aggh + (size_t)gw * Dd + lane * 4) = u;
}

// pack 8 scaled floats -> 8 halfs (16B)
__device__ __forceinline__ uint4 pack_half8(const float* v, float s) {
    __half2 p0 = __floats2half2_rn(v[0] * s, v[1] * s);
    __half2 p1 = __floats2half2_rn(v[2] * s, v[3] * s);
    __half2 p2 = __floats2half2_rn(v[4] * s, v[5] * s);
    __half2 p3 = __floats2half2_rn(v[6] * s, v[7] * s);
    uint4 u;
    u.x = *reinterpret_cast<unsigned*>(&p0);
    u.y = *reinterpret_cast<unsigned*>(&p1);
    u.z = *reinterpret_cast<unsigned*>(&p2);
    u.w = *reinterpret_cast<unsigned*>(&p3);
    return u;
}

// copy a 64x128 fp16 tile global -> smem (stride 136), coalesced uint4
__device__ __forceinline__ void stage_tile(__half* Ah, const __half* __restrict__ Ab,
                                           int tid) {
#pragma unroll
    for (int it = 0; it < 4; ++it) {
        int idx = it * 256 + tid;            // 1024 uint4 total
        int row = idx >> 4, c8 = idx & 15;
        uint4 u = __ldg(reinterpret_cast<const uint4*>(Ab + (size_t)row * Dd) + c8);
        *reinterpret_cast<uint4*>(Ah + row * 136 + c8 * 8) = u;
    }
}

// ---------------- layer-1 GEMM: smem-staged A, tensor cores -------------------
// C = aggh_r @ W1'_r ; epi: +bias, leaky, 1/3 mean; writes prescaled h1s
__launch_bounds__(256)
__global__ void k_gemm1(const float* __restrict__ b1) {
    __shared__ __align__(16) __half Ah[64 * 136];   // 17408 B
    __shared__ __align__(16) float  Cs[64 * 132];   // 33792 B
    int tid = threadIdx.x;
    int warp = tid >> 5;
    int ty = tid >> 4, tx = tid & 15;
    int wr = warp >> 1, wc = warp & 1;
    int n0 = blockIdx.x << 6;

    float hacc[4][8];
#pragma unroll
    for (int i = 0; i < 4; ++i)
#pragma unroll
        for (int j = 0; j < 8; ++j) hacc[i][j] = 0.f;

    for (int r = 0; r < Rr; ++r) {
        if (r > 0) __syncthreads();          // epilogue reads of Cs / Ah done
        stage_tile(Ah, g_aggh + ((size_t)r * Nn + n0) * Dd, tid);
        __syncthreads();

        wmma::fragment<wmma::accumulator, 16, 16, 16, float> acc[4];
#pragma unroll
        for (int f = 0; f < 4; ++f) wmma::fill_fragment(acc[f], 0.f);
        const __half* Bg = g_W1h + (size_t)r * Dd * Dd;
#pragma unroll
        for (int k = 0; k < 8; ++k) {
            wmma::fragment<wmma::matrix_a, 16, 16, 16, __half, wmma::row_major> af;
            wmma::load_matrix_sync(af, Ah + (wr * 16) * 136 + k * 16, 136);
#pragma unroll
            for (int f = 0; f < 4; ++f) {
                wmma::fragment<wmma::matrix_b, 16, 16, 16, __half, wmma::row_major> bf;
                wmma::load_matrix_sync(bf, Bg + (k * 16) * Dd + wc * 64 + f * 16, Dd);
                wmma::mma_sync(acc[f], af, bf, acc[f]);
            }
        }
#pragma unroll
        for (int f = 0; f < 4; ++f)
            wmma::store_matrix_sync(Cs + (wr * 16) * 132 + wc * 64 + f * 16, acc[f], 132,
                                    wmma::mem_row_major);
        __syncthreads();

        // epilogue: +bias, leaky, 1/3 mean
#pragma unroll
        for (int i = 0; i < 4; ++i) {
            int row = ty * 4 + i;
#pragma unroll
            for (int j = 0; j < 8; ++j) {
                int col = tx * 8 + j;
                float v = Cs[row * 132 + col] + b1[r * Dd + col];
                v = v >= 0.f ? v : SLOPEc * v;
                hacc[i][j] += v * (1.f / 3.f);
            }
        }
    }

    // write prescaled fp16 h1s for each relation
#pragma unroll
    for (int i = 0; i < 4; ++i) {
        int n = n0 + ty * 4 + i;
        if (n < Nn) {
#pragma unroll
            for (int r = 0; r < Rr; ++r) {
                float s = g_dinv_out[r * Nn + n];
                uint4 u = pack_half8(hacc[i], s);
                *reinterpret_cast<uint4*>(g_h1s + ((size_t)r * Nn + n) * Dd + tx * 8) = u;
            }
        }
    }
}

// ---------------- layer-2 GEMM + output projection: smem-staged A --------------
__launch_bounds__(256)
__global__ void k_gemm2(float* __restrict__ out) {
    __shared__ __align__(16) __half Ah[64 * 136];
    __shared__ __align__(16) float  Cs[64 * 68];
    int tid = threadIdx.x;
    int warp = tid >> 5;
    int ty = tid >> 4, tx = tid & 15;
    int wr = warp >> 1, wc = warp & 1;
    int n0 = blockIdx.x << 6;

    wmma::fragment<wmma::accumulator, 16, 16, 16, float> acc[2];
#pragma unroll
    for (int f = 0; f < 2; ++f) wmma::fill_fragment(acc[f], 0.f);

#pragma unroll 1
    for (int seg = 0; seg < 4; ++seg) {
        const __half* Ab = (seg < 3) ? (g_aggh + ((size_t)seg * Nn + n0) * Dd)
                                     : (g_xh + (size_t)n0 * Dd);
        const __half* Bb = (seg < 3) ? (g_Gh + (size_t)seg * Dd * OUTD) : g_Gxh;
        if (seg > 0) __syncthreads();
        stage_tile(Ah, Ab, tid);
        __syncthreads();
#pragma unroll
        for (int k = 0; k < 8; ++k) {
            wmma::fragment<wmma::matrix_a, 16, 16, 16, __half, wmma::row_major> af;
            wmma::load_matrix_sync(af, Ah + (wr * 16) * 136 + k * 16, 136);
#pragma unroll
            for (int f = 0; f < 2; ++f) {
                wmma::fragment<wmma::matrix_b, 16, 16, 16, __half, wmma::row_major> bf;
                wmma::load_matrix_sync(bf, Bb + (k * 16) * OUTD + wc * 32 + f * 16, OUTD);
                wmma::mma_sync(acc[f], af, bf, acc[f]);
            }
        }
    }
    __syncthreads();
#pragma unroll
    for (int f = 0; f < 2; ++f)
        wmma::store_matrix_sync(Cs + (wr * 16) * 68 + wc * 32 + f * 16, acc[f], 68,
                                wmma::mem_row_major);
    __syncthreads();

#pragma unroll
    for (int i = 0; i < 4; ++i) {
        int n = n0 + ty * 4 + i;
        if (n < Nn) {
            int row = ty * 4 + i;
            float4 o;
            o.x = Cs[row * 68 + tx * 4 + 0] + g_c[tx * 4 + 0];
            o.y = Cs[row * 68 + tx * 4 + 1] + g_c[tx * 4 + 1];
            o.z = Cs[row * 68 + tx * 4 + 2] + g_c[tx * 4 + 2];
            o.w = Cs[row * 68 + tx * 4 + 3] + g_c[tx * 4 + 3];
            *reinterpret_cast<float4*>(out + (size_t)n * OUTD + tx * 4) = o;
        }
    }
}

// ---------------- launch ------------------------------------------------------
extern "C" void kernel_launch(void* const* d_in, const int* in_sizes, int n_in,
                              void* d_out, int out_size) {
    const float* x    = (const float*)d_in[0];
    const int*   src  = (const int*)  d_in[1];
    const int*   dst  = (const int*)  d_in[2];
    const float* W1   = (const float*)d_in[3];
    const float* b1   = (const float*)d_in[4];
    const float* W2   = (const float*)d_in[5];
    const float* b2   = (const float*)d_in[6];
    const float* Wlin = (const float*)d_in[7];
    const float* blin = (const float*)d_in[8];
    float* out = (float*)d_out;

    k_init<<<(Rr * Nn + 255) / 256, 256>>>();
    k_degree<<<(Rr * Ee + 255) / 256, 256>>>(src, dst);
    dim3 rsgrid((Nn + 255) / 256, Rr);
    k_rowstart<<<rsgrid, 256>>>();
    k_csrfill<<<(Rr * Ee + 255) / 256, 256>>>(src, dst);
    k_prescale<<<(Nn * (Dd / 4) + 255) / 256, 256>>>(x);
    k_prep1<<<Rr * Dd, OUTD>>>(W2, Wlin);
    k_prep2<<<32, 256>>>(b2, Wlin, blin);
    k_prepw1<<<(Rr * Dd * Dd + 255) / 256, 256>>>(W1);

    const int gather_blocks = (Rr * Nn * 32 + 255) / 256;   // one warp per (r,n)
    // layer 1
    k_gather<<<gather_blocks, 256>>>(0);
    k_gemm1<<<(Nn + 63) / 64, 256>>>(b1);
    // layer 2
    k_gather<<<gather_blocks, 256>>>(1);
    k_gemm2<<<(Nn + 63) / 64, 256>>>(out);
}

// round 9
// speedup vs baseline: 1.1532x; 1.0428x over previous
#include <cuda_runtime.h>
#include <cuda_fp16.h>
#include <mma.h>
#include <cstdint>

using namespace nvcuda;

// Problem constants (fixed by dataset)
#define Nn 50000
#define Dd 128
#define Rr 3
#define Ee 800000
#define OUTD 64
#define ALPHAc 0.5f
#define BETA1c 0.6931471805599453f   // ln 2
#define BETA2c 0.4054651081081644f   // ln 1.5
#define SLOPEc 0.01f

// ---------------- scratch (device globals; no allocations allowed) ----------
__device__ __align__(256) __half g_xs  [(size_t)Rr * Nn * Dd];        // prescaled x (dinv_out)
__device__ __align__(256) __half g_h1s [(size_t)Rr * Nn * Dd];        // prescaled h1 (dinv_out)
__device__ __align__(256) __half g_aggh[((size_t)Rr * Nn + 64) * Dd]; // complete layer operand, padded
__device__ __align__(256) __half g_xh  [((size_t)Nn + 64) * Dd];      // plain fp16 x, padded
__device__ __align__(256) __half g_W1h [Rr * Dd * Dd];                // b1*W1 + (1-b1)*I
__device__ __align__(256) __half g_Gh  [Rr * Dd * OUTD];
__device__ __align__(256) __half g_Gxh [Dd * OUTD];
__device__ int   g_deg_out[Rr * Nn];
__device__ int   g_deg_in[Rr * Nn];
__device__ float g_dinv_out[Rr * Nn];
__device__ float g_dinv_in[Rr * Nn];
__device__ int   g_rowstart[Rr * Nn];
__device__ int   g_fillcur[Rr * Nn];
__device__ int   g_col[(size_t)Rr * Ee];
__device__ int   g_cursor[Rr];
__device__ float g_G[Rr * Dd * OUTD];
__device__ float g_c[OUTD];

// ---------------- init small state -------------------------------------------
__global__ void k_init() {
    int i = blockIdx.x * blockDim.x + threadIdx.x;
    if (i < Rr * Nn) { g_deg_out[i] = 0; g_deg_in[i] = 0; }
    if (i < Rr) g_cursor[i] = 0;
}

// ---------------- launch A: degree histogram + prep1 + prepw1 (independent) ---
#define DEG_BLOCKS  ((Rr * Ee + 255) / 256)                  // 9375
#define P1_BLOCKS   ((Rr * Dd * OUTD + 255) / 256)           // 96
#define PW1_BLOCKS  ((Rr * Dd * Dd + 255) / 256)             // 192
__global__ void k_degree_prep(const int* __restrict__ src, const int* __restrict__ dst,
                              const float* __restrict__ W2, const float* __restrict__ Wlin,
                              const float* __restrict__ W1) {
    int b = blockIdx.x;
    int t = threadIdx.x;
    if (b < DEG_BLOCKS) {
        int i = b * 256 + t;
        if (i >= Rr * Ee) return;
        int r = i / Ee;
        atomicAdd(&g_deg_out[r * Nn + src[i]], 1);
        atomicAdd(&g_deg_in [r * Nn + dst[i]], 1);
    } else if (b < DEG_BLOCKS + P1_BLOCKS) {
        // prep1: g_G[r][i][j] = b2*(W2_r@Wlin)[i][j] + (1-b2)*Wlin[i][j]
        int idx = (b - DEG_BLOCKS) * 256 + t;
        if (idx >= Rr * Dd * OUTD) return;
        int r = idx / (Dd * OUTD);
        int rem = idx % (Dd * OUTD);
        int i = rem / OUTD, j = rem % OUTD;
        const float* wrow = W2 + ((size_t)r * Dd + i) * Dd;
        float s = 0.f;
#pragma unroll 8
        for (int k = 0; k < Dd; ++k) s += wrow[k] * Wlin[k * OUTD + j];
        g_G[idx] = BETA2c * s + (1.f - BETA2c) * Wlin[rem];
    } else {
        // prepw1: W1' = b1*W1 + (1-b1)*I, fp16
        int idx = (b - DEG_BLOCKS - P1_BLOCKS) * 256 + t;
        if (idx >= Rr * Dd * Dd) return;
        int ij = idx % (Dd * Dd);
        int i = ij >> 7, j = ij & 127;
        float v = BETA1c * W1[idx] + ((i == j) ? (1.f - BETA1c) : 0.f);
        g_W1h[idx] = __float2half(v);
    }
}

// ---------------- launch B: row starts + dinv + prep2 --------------------------
#define RS_XBLOCKS ((Nn + 255) / 256)                        // 196
#define RS_BLOCKS  (RS_XBLOCKS * Rr)                         // 588
#define P2_BLOCKS  ((Dd * OUTD + 255) / 256)                 // 32
__global__ void k_rowstart_prep(const float* __restrict__ b2, const float* __restrict__ Wlin,
                                const float* __restrict__ blin) {
    int b = blockIdx.x;
    int t = threadIdx.x;
    if (b < RS_BLOCKS) {
        int r = b / RS_XBLOCKS;
        int n = (b % RS_XBLOCKS) * 256 + t;
        int lane = t & 31;
        int d = (n < Nn) ? g_deg_in[r * Nn + n] : 0;
        int incl = d;
#pragma unroll
        for (int o = 1; o < 32; o <<= 1) {
            int v = __shfl_up_sync(0xffffffffu, incl, o);
            if (lane >= o) incl += v;
        }
        int total = __shfl_sync(0xffffffffu, incl, 31);
        int base = 0;
        if (lane == 31) base = atomicAdd(&g_cursor[r], total);
        base = __shfl_sync(0xffffffffu, base, 31);
        if (n < Nn) {
            int start = r * Ee + base + incl - d;
            g_rowstart[r * Nn + n] = start;
            g_fillcur [r * Nn + n] = start;
            int di = d < 1 ? 1 : d;
            g_dinv_in[r * Nn + n] = rsqrtf((float)di);
            int doo = g_deg_out[r * Nn + n]; if (doo < 1) doo = 1;
            g_dinv_out[r * Nn + n] = rsqrtf((float)doo);
        }
    } else {
        // prep2: scale + fp16 convert G, Gx; compute c
        int idx = (b - RS_BLOCKS) * 256 + t;
        if (idx < Dd * OUTD) {
            float v0 = g_G[idx], v1 = g_G[Dd * OUTD + idx], v2 = g_G[2 * Dd * OUTD + idx];
            g_Gxh[idx] = __float2half((ALPHAc / 3.f) * (v0 + v1 + v2));
            const float sc = (1.f - ALPHAc) / 3.f;
            g_Gh[idx]                 = __float2half(v0 * sc);
            g_Gh[Dd * OUTD + idx]     = __float2half(v1 * sc);
            g_Gh[2 * Dd * OUTD + idx] = __float2half(v2 * sc);
        }
        if (idx < OUTD) {
            float cc = blin[idx];
            for (int k = 0; k < Dd; ++k)
                cc += (b2[k] + b2[Dd + k] + b2[2 * Dd + k]) * (1.f / 3.f) * Wlin[k * OUTD + idx];
            g_c[idx] = cc;
        }
    }
}

// ---------------- launch C: CSR fill + prescale (both depend on rowstart) -----
#define CF_BLOCKS  ((Rr * Ee + 255) / 256)                   // 9375
#define PS_BLOCKS  ((Nn * (Dd / 4) + 255) / 256)             // 6250
__global__ void k_csrfill_prescale(const int* __restrict__ src, const int* __restrict__ dst,
                                   const float* __restrict__ x) {
    int b = blockIdx.x;
    int t = threadIdx.x;
    if (b < CF_BLOCKS) {
        int i = b * 256 + t;
        if (i >= Rr * Ee) return;
        int r = i / Ee;
        int pos = atomicAdd(&g_fillcur[r * Nn + dst[i]], 1);
        g_col[pos] = src[i];
    } else {
        // prescale: read x once, write xh + 3 prescaled copies
        int i = (b - CF_BLOCKS) * 256 + t;
        if (i >= Nn * (Dd / 4)) return;
        int c4 = i & 31;
        int n = i >> 5;
        float4 v = __ldg(reinterpret_cast<const float4*>(x + (size_t)n * Dd) + c4);
        __half2 q0 = __floats2half2_rn(v.x, v.y);
        __half2 q1 = __floats2half2_rn(v.z, v.w);
        uint2 w;
        w.x = *reinterpret_cast<unsigned*>(&q0);
        w.y = *reinterpret_cast<unsigned*>(&q1);
        *reinterpret_cast<uint2*>(g_xh + (size_t)n * Dd + c4 * 4) = w;
#pragma unroll
        for (int r = 0; r < Rr; ++r) {
            float s = __ldg(g_dinv_out + r * Nn + n);
            __half2 p0 = __floats2half2_rn(v.x * s, v.y * s);
            __half2 p1 = __floats2half2_rn(v.z * s, v.w * s);
            uint2 u;
            u.x = *reinterpret_cast<unsigned*>(&p0);
            u.y = *reinterpret_cast<unsigned*>(&p1);
            *reinterpret_cast<uint2*>(g_xs + ((size_t)r * Nn + n) * Dd + c4 * 4) = u;
        }
    }
}

// ---------------- fp16 gather helpers ------------------------------------------
__device__ __forceinline__ void acc_h4(float4& acc, uint2 u) {
    __half2 a = *reinterpret_cast<__half2*>(&u.x);
    __half2 b = *reinterpret_cast<__half2*>(&u.y);
    float2 fa = __half22float2(a), fb = __half22float2(b);
    acc.x += fa.x; acc.y += fa.y; acc.z += fb.x; acc.w += fb.y;
}

// ---------------- gather: one warp per (r,n); produces COMPLETE layer operand --
// which=0: aggh = (1-a)*dinv_in*sum + a*x   (layer-1 rst, fp16)
// which=1: aggh = dinv_in*sum               (layer-2 A operand)
__launch_bounds__(256)
__global__ void k_gather(int which) {
    int gw = (blockIdx.x * blockDim.x + threadIdx.x) >> 5;   // (r,n) index
    if (gw >= Rr * Nn) return;
    int lane = threadIdx.x & 31;
    int n = gw % Nn;
    const __half* base = (which ? g_h1s : g_xs) + (size_t)(gw / Nn) * Nn * Dd;

    int beg = __ldg(g_rowstart + gw);
    int end = beg + __ldg(g_deg_in + gw);
    float4 acc = make_float4(0.f, 0.f, 0.f, 0.f);
    int e = beg;
#pragma unroll 1
    for (; e + 4 <= end; e += 4) {
        int s0 = __ldg(g_col + e);
        int s1 = __ldg(g_col + e + 1);
        int s2 = __ldg(g_col + e + 2);
        int s3 = __ldg(g_col + e + 3);
        uint2 u0 = __ldg(reinterpret_cast<const uint2*>(base + (size_t)s0 * Dd) + lane);
        uint2 u1 = __ldg(reinterpret_cast<const uint2*>(base + (size_t)s1 * Dd) + lane);
        uint2 u2 = __ldg(reinterpret_cast<const uint2*>(base + (size_t)s2 * Dd) + lane);
        uint2 u3 = __ldg(reinterpret_cast<const uint2*>(base + (size_t)s3 * Dd) + lane);
        acc_h4(acc, u0); acc_h4(acc, u1); acc_h4(acc, u2); acc_h4(acc, u3);
    }
#pragma unroll 1
    for (; e < end; ++e) {
        int s0 = __ldg(g_col + e);
        uint2 u0 = __ldg(reinterpret_cast<const uint2*>(base + (size_t)s0 * Dd) + lane);
        acc_h4(acc, u0);
    }
    float sc = __ldg(g_dinv_in + gw) * (which ? 1.f : (1.f - ALPHAc));
    float4 o;
    if (which) {
        o.x = acc.x * sc; o.y = acc.y * sc; o.z = acc.z * sc; o.w = acc.w * sc;
    } else {
        uint2 xv = __ldg(reinterpret_cast<const uint2*>(g_xh + (size_t)n * Dd) + lane);
        float4 xf = make_float4(0.f, 0.f, 0.f, 0.f);
        acc_h4(xf, xv);
        o.x = acc.x * sc + ALPHAc * xf.x;
        o.y = acc.y * sc + ALPHAc * xf.y;
        o.z = acc.z * sc + ALPHAc * xf.z;
        o.w = acc.w * sc + ALPHAc * xf.w;
    }
    __half2 p0 = __floats2half2_rn(o.x, o.y);
    __half2 p1 = __floats2half2_rn(o.z, o.w);
    uint2 u;
    u.x = *reinterpret_cast<unsigned*>(&p0);
    u.y = *reinterpret_cast<unsigned*>(&p1);
    *reinterpret_cast<uint2*>(g_aggh + (size_t)gw * Dd + lane * 4) = u;
}

// pack 8 scaled floats -> 8 halfs (16B)
__device__ __forceinline__ uint4 pack_half8(const float* v, float s) {
    __half2 p0 = __floats2half2_rn(v[0] * s, v[1] * s);
    __half2 p1 = __floats2half2_rn(v[2] * s, v[3] * s);
    __half2 p2 = __floats2half2_rn(v[4] * s, v[5] * s);
    __half2 p3 = __floats2half2_rn(v[6] * s, v[7] * s);
    uint4 u;
    u.x = *reinterpret_cast<unsigned*>(&p0);
    u.y = *reinterpret_cast<unsigned*>(&p1);
    u.z = *reinterpret_cast<unsigned*>(&p2);
    u.w = *reinterpret_cast<unsigned*>(&p3);
    return u;
}

// copy a 64x128 fp16 tile global -> smem (stride 136), coalesced uint4
__device__ __forceinline__ void stage_tile(__half* Ah, const __half* __restrict__ Ab,
                                           int tid) {
#pragma unroll
    for (int it = 0; it < 4; ++it) {
        int idx = it * 256 + tid;            // 1024 uint4 total
        int row = idx >> 4, c8 = idx & 15;
        uint4 u = __ldg(reinterpret_cast<const uint4*>(Ab + (size_t)row * Dd) + c8);
        *reinterpret_cast<uint4*>(Ah + row * 136 + c8 * 8) = u;
    }
}

// ---------------- layer-1 GEMM: smem-staged A, tensor cores -------------------
__launch_bounds__(256)
__global__ void k_gemm1(const float* __restrict__ b1) {
    __shared__ __align__(16) __half Ah[64 * 136];   // 17408 B
    __shared__ __align__(16) float  Cs[64 * 132];   // 33792 B
    int tid = threadIdx.x;
    int warp = tid >> 5;
    int ty = tid >> 4, tx = tid & 15;
    int wr = warp >> 1, wc = warp & 1;
    int n0 = blockIdx.x << 6;

    float hacc[4][8];
#pragma unroll
    for (int i = 0; i < 4; ++i)
#pragma unroll
        for (int j = 0; j < 8; ++j) hacc[i][j] = 0.f;

    for (int r = 0; r < Rr; ++r) {
        if (r > 0) __syncthreads();          // epilogue reads of Cs / Ah done
        stage_tile(Ah, g_aggh + ((size_t)r * Nn + n0) * Dd, tid);
        __syncthreads();

        wmma::fragment<wmma::accumulator, 16, 16, 16, float> acc[4];
#pragma unroll
        for (int f = 0; f < 4; ++f) wmma::fill_fragment(acc[f], 0.f);
        const __half* Bg = g_W1h + (size_t)r * Dd * Dd;
#pragma unroll
        for (int k = 0; k < 8; ++k) {
            wmma::fragment<wmma::matrix_a, 16, 16, 16, __half, wmma::row_major> af;
            wmma::load_matrix_sync(af, Ah + (wr * 16) * 136 + k * 16, 136);
#pragma unroll
            for (int f = 0; f < 4; ++f) {
                wmma::fragment<wmma::matrix_b, 16, 16, 16, __half, wmma::row_major> bf;
                wmma::load_matrix_sync(bf, Bg + (k * 16) * Dd + wc * 64 + f * 16, Dd);
                wmma::mma_sync(acc[f], af, bf, acc[f]);
            }
        }
#pragma unroll
        for (int f = 0; f < 4; ++f)
            wmma::store_matrix_sync(Cs + (wr * 16) * 132 + wc * 64 + f * 16, acc[f], 132,
                                    wmma::mem_row_major);
        __syncthreads();

        // epilogue: +bias, leaky, 1/3 mean
#pragma unroll
        for (int i = 0; i < 4; ++i) {
            int row = ty * 4 + i;
#pragma unroll
            for (int j = 0; j < 8; ++j) {
                int col = tx * 8 + j;
                float v = Cs[row * 132 + col] + b1[r * Dd + col];
                v = v >= 0.f ? v : SLOPEc * v;
                hacc[i][j] += v * (1.f / 3.f);
            }
        }
    }

    // write prescaled fp16 h1s for each relation
#pragma unroll
    for (int i = 0; i < 4; ++i) {
        int n = n0 + ty * 4 + i;
        if (n < Nn) {
#pragma unroll
            for (int r = 0; r < Rr; ++r) {
                float s = g_dinv_out[r * Nn + n];
                uint4 u = pack_half8(hacc[i], s);
                *reinterpret_cast<uint4*>(g_h1s + ((size_t)r * Nn + n) * Dd + tx * 8) = u;
            }
        }
    }
}

// ---------------- layer-2 GEMM + output projection: smem-staged A --------------
__launch_bounds__(256)
__global__ void k_gemm2(float* __restrict__ out) {
    __shared__ __align__(16) __half Ah[64 * 136];
    __shared__ __align__(16) float  Cs[64 * 68];
    int tid = threadIdx.x;
    int warp = tid >> 5;
    int ty = tid >> 4, tx = tid & 15;
    int wr = warp >> 1, wc = warp & 1;
    int n0 = blockIdx.x << 6;

    wmma::fragment<wmma::accumulator, 16, 16, 16, float> acc[2];
#pragma unroll
    for (int f = 0; f < 2; ++f) wmma::fill_fragment(acc[f], 0.f);

#pragma unroll 1
    for (int seg = 0; seg < 4; ++seg) {
        const __half* Ab = (seg < 3) ? (g_aggh + ((size_t)seg * Nn + n0) * Dd)
                                     : (g_xh + (size_t)n0 * Dd);
        const __half* Bb = (seg < 3) ? (g_Gh + (size_t)seg * Dd * OUTD) : g_Gxh;
        if (seg > 0) __syncthreads();
        stage_tile(Ah, Ab, tid);
        __syncthreads();
#pragma unroll
        for (int k = 0; k < 8; ++k) {
            wmma::fragment<wmma::matrix_a, 16, 16, 16, __half, wmma::row_major> af;
            wmma::load_matrix_sync(af, Ah + (wr * 16) * 136 + k * 16, 136);
#pragma unroll
            for (int f = 0; f < 2; ++f) {
                wmma::fragment<wmma::matrix_b, 16, 16, 16, __half, wmma::row_major> bf;
                wmma::load_matrix_sync(bf, Bb + (k * 16) * OUTD + wc * 32 + f * 16, OUTD);
                wmma::mma_sync(acc[f], af, bf, acc[f]);
            }
        }
    }
    __syncthreads();
#pragma unroll
    for (int f = 0; f < 2; ++f)
        wmma::store_matrix_sync(Cs + (wr * 16) * 68 + wc * 32 + f * 16, acc[f], 68,
                                wmma::mem_row_major);
    __syncthreads();

#pragma unroll
    for (int i = 0; i < 4; ++i) {
        int n = n0 + ty * 4 + i;
        if (n < Nn) {
            int row = ty * 4 + i;
            float4 o;
            o.x = Cs[row * 68 + tx * 4 + 0] + g_c[tx * 4 + 0];
            o.y = Cs[row * 68 + tx * 4 + 1] + g_c[tx * 4 + 1];
            o.z = Cs[row * 68 + tx * 4 + 2] + g_c[tx * 4 + 2];
            o.w = Cs[row * 68 + tx * 4 + 3] + g_c[tx * 4 + 3];
            *reinterpret_cast<float4*>(out + (size_t)n * OUTD + tx * 4) = o;
        }
    }
}

// ---------------- launch ------------------------------------------------------
extern "C" void kernel_launch(void* const* d_in, const int* in_sizes, int n_in,
                              void* d_out, int out_size) {
    const float* x    = (const float*)d_in[0];
    const int*   src  = (const int*)  d_in[1];
    const int*   dst  = (const int*)  d_in[2];
    const float* W1   = (const float*)d_in[3];
    const float* b1   = (const float*)d_in[4];
    const float* W2   = (const float*)d_in[5];
    const float* b2   = (const float*)d_in[6];
    const float* Wlin = (const float*)d_in[7];
    const float* blin = (const float*)d_in[8];
    float* out = (float*)d_out;

    k_init<<<(Rr * Nn + 255) / 256, 256>>>();
    k_degree_prep<<<DEG_BLOCKS + P1_BLOCKS + PW1_BLOCKS, 256>>>(src, dst, W2, Wlin, W1);
    k_rowstart_prep<<<RS_BLOCKS + P2_BLOCKS, 256>>>(b2, Wlin, blin);
    k_csrfill_prescale<<<CF_BLOCKS + PS_BLOCKS, 256>>>(src, dst, x);

    const int gather_blocks = (Rr * Nn * 32 + 255) / 256;   // one warp per (r,n)
    // layer 1
    k_gather<<<gather_blocks, 256>>>(0);
    k_gemm1<<<(Nn + 63) / 64, 256>>>(b1);
    // layer 2
    k_gather<<<gather_blocks, 256>>>(1);
    k_gemm2<<<(Nn + 63) / 64, 256>>>(out);
}